// round 2
// baseline (speedup 1.0000x reference)
#include <cuda_runtime.h>
#include <math.h>
#include <stdint.h>

#define Bv    8
#define Tv    4096
#define DIN   64
#define DRES  1024
#define NCTA  128
#define ROWS  8      // output rows of W per CTA (128*8 = 1024)
#define NTH   256

// step-completion counters, zeroed each launch via cudaMemsetAsync
__device__ int g_flags[Tv];

#define SMEM_FLOATS (ROWS*DRES + Bv*DRES + ROWS*DIN + Bv*DIN + 8*16 + 8)
#define SMEM_BYTES  (SMEM_FLOATS * 4)

__device__ __forceinline__ void cp16(uint32_t dst, const void* src) {
    asm volatile("cp.async.cg.shared.global [%0], [%1], 16;\n" :: "r"(dst), "l"(src));
}
__device__ __forceinline__ void cp_commit() {
    asm volatile("cp.async.commit_group;\n");
}
__device__ __forceinline__ void cp_wait_all() {
    asm volatile("cp.async.wait_group 0;\n" ::: "memory");
}

__global__ void __launch_bounds__(NTH, 1) esn_kernel(
    const float* __restrict__ u,      // [B, T, DIN]
    const float* __restrict__ w_in,   // [DRES, DIN]
    const float* __restrict__ w,      // [DRES, DRES]
    const float* __restrict__ w_bias, // [DRES]
    float* __restrict__ out)          // [B, T, DRES]  (also serves as h history)
{
    extern __shared__ float smem[];
    float* Wsh    = smem;                    // [ROWS][DRES]
    float* Hsh    = Wsh   + ROWS * DRES;     // [Bv][DRES]
    float* WINsh  = Hsh   + Bv   * DRES;     // [ROWS][DIN]
    float* Ush    = WINsh + ROWS * DIN;      // [Bv][DIN]
    float* red    = Ush   + Bv   * DIN;      // [8 warps][16]
    float* biassh = red   + 8 * 16;          // [ROWS]

    const int tid  = threadIdx.x;
    const int wrp  = tid >> 5;
    const int lane = tid & 31;
    const int cta  = blockIdx.x;
    const int r_base = cta * ROWS;

    // ---- one-time loads: W slice, w_in slice, bias ----
    {
        const float4* wsrc = (const float4*)(w + (size_t)r_base * DRES);
        float4* wdst = (float4*)Wsh;
        #pragma unroll
        for (int q = 0; q < (ROWS*DRES/4)/NTH; ++q)
            wdst[tid + q*NTH] = wsrc[tid + q*NTH];
        if (tid < ROWS*DIN/4)
            ((float4*)WINsh)[tid] = ((const float4*)(w_in + r_base * DIN))[tid];
        if (tid < ROWS)
            biassh[tid] = w_bias[r_base + tid];
    }
    __syncthreads();

    // warp -> (row-group, batch-group, k-half) tile assignment
    const int rg = (wrp >> 2) & 1;
    const int bg = (wrp >> 1) & 1;
    const int kh = wrp & 1;
    const int r0 = rg * 4;
    const int b0 = bg * 4;

    const uint32_t HshA = (uint32_t)__cvta_generic_to_shared(Hsh);
    const uint32_t UshA = (uint32_t)__cvta_generic_to_shared(Ush);

    for (int t = 0; t < Tv; ++t) {
        // prefetch u[:, t, :] (no dependency on previous step)
        if (tid < Bv*DIN/4) {
            int b = tid >> 4;               // 16 float4 per batch row
            int i = (tid & 15) * 4;
            cp16(UshA + tid*16, u + ((size_t)b*Tv + t)*DIN + i);
        }
        cp_commit();

        if (t > 0) {
            // wait for all CTAs to have published h_{t-1}
            if (tid == 0) {
                volatile int* f = &g_flags[t-1];
                while (*f < NCTA) { }
                __threadfence();
            }
            __syncthreads();
            // load H = out[:, t-1, :]  (32 KB, straight from L2 via .cg)
            #pragma unroll
            for (int q = 0; q < 8; ++q) {
                int idx = tid + q * NTH;     // 0..2047 float4
                int b   = idx >> 8;          // 256 float4 per batch
                int kk  = (idx & 255) * 4;
                cp16(HshA + idx*16, out + ((size_t)b*Tv + (t-1))*DRES + kk);
            }
            cp_commit();
        }
        cp_wait_all();
        __syncthreads();

        // ---- compute: 4x4 (rows x batches) register tile, k-half per warp ----
        float acc[16];
        #pragma unroll
        for (int i = 0; i < 16; ++i) acc[i] = 0.f;

        if (t > 0) {
            #pragma unroll
            for (int j = 0; j < 4; ++j) {
                const int kb = kh*512 + j*128 + lane*4;   // conflict-free LDS.128
                float4 wv[4], hv[4];
                #pragma unroll
                for (int rr = 0; rr < 4; ++rr)
                    wv[rr] = *(const float4*)&Wsh[(r0+rr)*DRES + kb];
                #pragma unroll
                for (int bb = 0; bb < 4; ++bb)
                    hv[bb] = *(const float4*)&Hsh[(b0+bb)*DRES + kb];
                #pragma unroll
                for (int rr = 0; rr < 4; ++rr)
                    #pragma unroll
                    for (int bb = 0; bb < 4; ++bb) {
                        float s = acc[rr*4+bb];
                        s = fmaf(wv[rr].x, hv[bb].x, s);
                        s = fmaf(wv[rr].y, hv[bb].y, s);
                        s = fmaf(wv[rr].z, hv[bb].z, s);
                        s = fmaf(wv[rr].w, hv[bb].w, s);
                        acc[rr*4+bb] = s;
                    }
            }
        }
        // fold input projection (k = 0..63) into k-half-0 warps
        if (kh == 0) {
            const int i2 = lane * 2;
            float2 wv[4], uv[4];
            #pragma unroll
            for (int rr = 0; rr < 4; ++rr)
                wv[rr] = *(const float2*)&WINsh[(r0+rr)*DIN + i2];
            #pragma unroll
            for (int bb = 0; bb < 4; ++bb)
                uv[bb] = *(const float2*)&Ush[(b0+bb)*DIN + i2];
            #pragma unroll
            for (int rr = 0; rr < 4; ++rr)
                #pragma unroll
                for (int bb = 0; bb < 4; ++bb) {
                    float s = acc[rr*4+bb];
                    s = fmaf(wv[rr].x, uv[bb].x, s);
                    s = fmaf(wv[rr].y, uv[bb].y, s);
                    acc[rr*4+bb] = s;
                }
        }

        // warp-level k reduction
        #pragma unroll
        for (int off = 16; off; off >>= 1)
            #pragma unroll
            for (int i = 0; i < 16; ++i)
                acc[i] += __shfl_xor_sync(0xffffffffu, acc[i], off);
        if (lane == 0) {
            #pragma unroll
            for (int i = 0; i < 16; ++i) red[wrp*16 + i] = acc[i];
        }
        __syncthreads();

        // combine k-halves, bias + tanh, publish
        if (tid < 64) {
            const int tile = tid >> 4;      // = rg*2 + bg
            const int idx  = tid & 15;
            float v = red[(tile*2)*16 + idx] + red[(tile*2+1)*16 + idx];
            const int rl = ((tile >> 1) * 4) + (idx >> 2);
            const int b  = ((tile & 1) * 4) + (idx & 3);
            v = tanhf(v + biassh[rl]);
            out[((size_t)b*Tv + t)*DRES + r_base + rl] = v;
        }
        __syncthreads();                    // all stores of this CTA done
        if (tid == 0) {
            __threadfence();                // release: stores visible before flag
            atomicAdd(&g_flags[t], 1);      // RED (result unused)
        }
    }
}

extern "C" void kernel_launch(void* const* d_in, const int* in_sizes, int n_in,
                              void* d_out, int out_size) {
    const float* u      = (const float*)d_in[0];
    const float* w_in   = (const float*)d_in[1];
    const float* w      = (const float*)d_in[2];
    const float* w_bias = (const float*)d_in[3];
    float* out = (float*)d_out;

    void* flagsPtr = nullptr;
    cudaGetSymbolAddress(&flagsPtr, g_flags);
    cudaMemsetAsync(flagsPtr, 0, Tv * sizeof(int), 0);

    cudaFuncSetAttribute(esn_kernel,
                         cudaFuncAttributeMaxDynamicSharedMemorySize, SMEM_BYTES);
    esn_kernel<<<NCTA, NTH, SMEM_BYTES>>>(u, w_in, w, w_bias, out);
}

// round 3
// speedup vs baseline: 1.2986x; 1.2986x over previous
#include <cuda_runtime.h>
#include <cuda/atomic>
#include <math.h>
#include <stdint.h>

#define Bv    8
#define Tv    4096
#define DIN   64
#define DRES  1024
#define NCTA  128
#define ROWS  8        // rows of W per CTA
#define NTH   512      // 16 warps: 4 k-quarter groups x 4 warps (rg x bg)
#define NQ    4
#define CTAS_PER_Q (NCTA / NQ)   // 32

// per-quarter, per-step completion counters (zeroed each launch)
__device__ int g_flags[NQ * Tv];

// smem: Hsh[8][1024] + Ush[8][64] + red[2][16][16]
#define SMEM_FLOATS (Bv*DRES + Bv*DIN + 2*16*16)
#define SMEM_BYTES  (SMEM_FLOATS * 4)

__device__ __forceinline__ void cp16(uint32_t dst, const void* src) {
    asm volatile("cp.async.cg.shared.global [%0], [%1], 16;\n" :: "r"(dst), "l"(src));
}
__device__ __forceinline__ void cp_commit() {
    asm volatile("cp.async.commit_group;\n");
}
__device__ __forceinline__ void cp_wait_all() {
    asm volatile("cp.async.wait_group 0;\n" ::: "memory");
}
__device__ __forceinline__ void barn(int id, int cnt) {
    asm volatile("bar.sync %0, %1;" :: "r"(id), "r"(cnt) : "memory");
}
__device__ __forceinline__ float fast_tanh(float x) {
    // 1 - 2/(exp(2x)+1); __expf abs err ~1e-7 relative -> tanh abs err ~1e-6
    float e = __expf(2.0f * x);
    return 1.0f - __fdividef(2.0f, e + 1.0f);
}

__global__ void __launch_bounds__(NTH, 1) esn_kernel(
    const float* __restrict__ u,      // [B, T, DIN]
    const float* __restrict__ w_in,   // [DRES, DIN]
    const float* __restrict__ w,      // [DRES, DRES]
    const float* __restrict__ w_bias, // [DRES]
    float* __restrict__ out)          // [B, T, DRES] (also h history)
{
    extern __shared__ float smem[];
    float* Hsh = smem;                 // [8][1024]
    float* Ush = Hsh + Bv * DRES;      // [8][64]
    float* red = Ush + Bv * DIN;       // [2][16][16]

    const int tid  = threadIdx.x;
    const int wrp  = tid >> 5;
    const int lane = tid & 31;
    const int q    = wrp >> 2;         // k-quarter group 0..3
    const int wq   = wrp & 3;          // warp within group
    const int rg   = wq >> 1;
    const int bg   = wq & 1;
    const int r0   = rg * 4;           // local row base (0 or 4)
    const int b0   = bg * 4;           // batch base (0 or 4)
    const int cta  = blockIdx.x;
    const int r_base = cta * ROWS;
    const int myq  = cta >> 5;         // quarter this CTA's rows belong to
    const int g    = tid & 127;        // thread index within group

    // ---- W slice held in registers for all 4096 steps ----
    float4 Wreg[4][2];
    #pragma unroll
    for (int rr = 0; rr < 4; ++rr)
        #pragma unroll
        for (int j = 0; j < 2; ++j)
            Wreg[rr][j] = *(const float4*)(w + (size_t)(r_base + r0 + rr) * DRES
                                             + q * 256 + j * 128 + lane * 4);
    float2 winreg[4];
    if (q == 3) {
        #pragma unroll
        for (int rr = 0; rr < 4; ++rr)
            winreg[rr] = *(const float2*)(w_in + (r_base + r0 + rr) * DIN + lane * 2);
    }

    // combine-stage per-thread constants (tid < 64)
    float biasr = 0.f;
    size_t obase = 0;
    if (tid < 64) {
        int tile = tid >> 4, idx = tid & 15;
        int rl = (tile >> 1) * 4 + (idx >> 2);
        int b  = (tile & 1) * 4 + (idx & 3);
        biasr = w_bias[r_base + rl];
        obase = (size_t)b * Tv * DRES + r_base + rl;
    }

    const uint32_t HshA = (uint32_t)__cvta_generic_to_shared(Hsh);
    const uint32_t UshA = (uint32_t)__cvta_generic_to_shared(Ush);

    for (int t = 0; t < Tv; ++t) {
        if (t > 0) {
            // group q waits for its h-quarter producers (32 CTAs)
            if (wq == 0) {
                cuda::atomic_ref<int, cuda::thread_scope_device>
                    f(g_flags[q * Tv + (t - 1)]);
                while (f.load(cuda::memory_order_acquire) < CTAS_PER_Q) { }
            }
            barn(q + 1, 128);                       // propagate acquire to group
            if (q == 3) {                           // u prefetch (safe after bar)
                int b = g >> 4, i = (g & 15) * 4;
                cp16(UshA + (b * DIN + i) * 4,
                     u + ((size_t)b * Tv + t) * DIN + i);
            }
            // load this group's 8KB H quarter (4 x float4 per thread)
            #pragma unroll
            for (int v = 0; v < 4; ++v) {
                int f4 = v * 128 + g;
                int b  = f4 >> 6;
                int kk = (f4 & 63) * 4;
                cp16(HshA + (b * DRES + q * 256 + kk) * 4,
                     out + ((size_t)b * Tv + (t - 1)) * DRES + q * 256 + kk);
            }
        } else if (q == 3) {
            int b = g >> 4, i = (g & 15) * 4;
            cp16(UshA + (b * DIN + i) * 4, u + ((size_t)b * Tv + t) * DIN + i);
        }
        cp_commit();
        cp_wait_all();
        barn(q + 1, 128);                           // group-wide smem visibility

        // ---- compute: 4 rows x 4 batches, this warp's k-quarter ----
        float acc[16];
        #pragma unroll
        for (int i = 0; i < 16; ++i) acc[i] = 0.f;

        if (t > 0) {
            #pragma unroll
            for (int j = 0; j < 2; ++j) {
                float4 hv[4];
                #pragma unroll
                for (int bb = 0; bb < 4; ++bb)
                    hv[bb] = *(const float4*)&Hsh[(b0 + bb) * DRES
                                                  + q * 256 + j * 128 + lane * 4];
                #pragma unroll
                for (int rr = 0; rr < 4; ++rr) {
                    const float4 wv = Wreg[rr][j];
                    #pragma unroll
                    for (int bb = 0; bb < 4; ++bb) {
                        float s = acc[rr * 4 + bb];
                        s = fmaf(wv.x, hv[bb].x, s);
                        s = fmaf(wv.y, hv[bb].y, s);
                        s = fmaf(wv.z, hv[bb].z, s);
                        s = fmaf(wv.w, hv[bb].w, s);
                        acc[rr * 4 + bb] = s;
                    }
                }
            }
        }
        if (q == 3) {                                // fold input projection
            float2 uv[4];
            #pragma unroll
            for (int bb = 0; bb < 4; ++bb)
                uv[bb] = *(const float2*)&Ush[(b0 + bb) * DIN + lane * 2];
            #pragma unroll
            for (int rr = 0; rr < 4; ++rr)
                #pragma unroll
                for (int bb = 0; bb < 4; ++bb) {
                    float s = acc[rr * 4 + bb];
                    s = fmaf(winreg[rr].x, uv[bb].x, s);
                    s = fmaf(winreg[rr].y, uv[bb].y, s);
                    acc[rr * 4 + bb] = s;
                }
        }

        // warp k-reduction
        #pragma unroll
        for (int off = 16; off; off >>= 1)
            #pragma unroll
            for (int i = 0; i < 16; ++i)
                acc[i] += __shfl_xor_sync(0xffffffffu, acc[i], off);

        float* redt = red + (t & 1) * 256;           // double-buffered
        if (lane == 0) {
            #pragma unroll
            for (int i = 0; i < 16; ++i) redt[wrp * 16 + i] = acc[i];
        }
        __syncthreads();                             // red visible CTA-wide

        // combine quarters, bias + tanh, publish
        if (tid < 64) {
            int tile = tid >> 4, idx = tid & 15;
            float v = redt[(0 * 4 + tile) * 16 + idx]
                    + redt[(1 * 4 + tile) * 16 + idx]
                    + redt[(2 * 4 + tile) * 16 + idx]
                    + redt[(3 * 4 + tile) * 16 + idx];
            v = fast_tanh(v + biasr);
            out[obase + (size_t)t * DRES] = v;
            barn(6, 64);                             // order stores before flag
            if (tid == 0) {
                cuda::atomic_ref<int, cuda::thread_scope_device>
                    f(g_flags[myq * Tv + t]);
                f.fetch_add(1, cuda::memory_order_release);
            }
        }
    }
}

extern "C" void kernel_launch(void* const* d_in, const int* in_sizes, int n_in,
                              void* d_out, int out_size) {
    const float* u      = (const float*)d_in[0];
    const float* w_in   = (const float*)d_in[1];
    const float* w      = (const float*)d_in[2];
    const float* w_bias = (const float*)d_in[3];
    float* out = (float*)d_out;

    void* flagsPtr = nullptr;
    cudaGetSymbolAddress(&flagsPtr, g_flags);
    cudaMemsetAsync(flagsPtr, 0, NQ * Tv * sizeof(int), 0);

    cudaFuncSetAttribute(esn_kernel,
                         cudaFuncAttributeMaxDynamicSharedMemorySize, SMEM_BYTES);
    esn_kernel<<<NCTA, NTH, SMEM_BYTES>>>(u, w_in, w, w_bias, out);
}